// round 1
// baseline (speedup 1.0000x reference)
#include <cuda_runtime.h>
#include <cstdint>

#define BB 8
#define LL 4096
#define TT 128
#define DH 1024
#define DG 256
#define DP 256

// Scratch (static __device__ — no allocations allowed)
__device__ float g_Q[BB * TT * DP];    // 1 MB   : G @ Wq
__device__ float g_Qp[BB * TT * DH];   // 4 MB   : Q @ Wk^T  (folded query)
__device__ float g_S[BB * TT * LL];    // 16 MB  : logits -> softmax in place
__device__ int   g_mask_kind;          // 0=bool8, 1=int32, 2=float32

__device__ __forceinline__ uint32_t f2tf(float f) {
    uint32_t u;
    asm("cvt.rna.tf32.f32 %0, %1;" : "=r"(u) : "f"(f));
    return u;
}

__device__ __forceinline__ void mma8(float* c, const uint32_t* a, const uint32_t* b) {
    asm volatile(
        "mma.sync.aligned.m16n8k8.row.col.f32.tf32.tf32.f32 "
        "{%0,%1,%2,%3}, {%4,%5,%6,%7}, {%8,%9}, {%0,%1,%2,%3};"
        : "+f"(c[0]), "+f"(c[1]), "+f"(c[2]), "+f"(c[3])
        : "r"(a[0]), "r"(a[1]), "r"(a[2]), "r"(a[3]), "r"(b[0]), "r"(b[1]));
}

// Detect how the bool mask was materialized by the harness.
__global__ void detect_mask_kernel(const uint32_t* __restrict__ m) {
    if (threadIdx.x == 0 && blockIdx.x == 0) {
        bool isInt = true, isFloat = true;
        for (int i = 0; i < 256; i++) {
            uint32_t v = m[i];
            if (v != 0u && v != 1u) isInt = false;
            if (v != 0u && v != 0x3f800000u) isFloat = false;
        }
        g_mask_kind = isInt ? 1 : (isFloat ? 2 : 0);
    }
}

// Generic tf32 tile GEMM:  C = A(MxK) * op(B),  NT: B is [N,K] (C=A*B^T), NN: B is [K,N].
// BM=BN=64, BK=32, 128 threads (4 warps, 2x2, warp tile 32x32).
// EPI: 0 = plain store, 1 = scale + mask(-inf) store (logits).
template <bool NT, int EPI>
__global__ __launch_bounds__(128) void gemm_tf32_kernel(
    const float* __restrict__ A, const float* __restrict__ B, float* __restrict__ C,
    int M, int N, int K, int lda, int ldb, int ldc,
    long strideA, long strideB, long strideC,
    const void* __restrict__ maskp, float scale)
{
    const int b = blockIdx.z;
    A += (long)b * strideA;
    B += (long)b * strideB;
    C += (long)b * strideC;

    __shared__ float As[64 * 36];
    __shared__ float Bs[NT ? 64 * 36 : 32 * 68];

    const int tid  = threadIdx.x;
    const int m0   = blockIdx.y * 64;
    const int n0   = blockIdx.x * 64;
    const int warp = tid >> 5, lane = tid & 31;
    const int wm = (warp >> 1) * 32, wn = (warp & 1) * 32;
    const int g  = lane >> 2, tg = lane & 3;

    float acc[2][4][4];
    #pragma unroll
    for (int i = 0; i < 2; i++)
        #pragma unroll
        for (int j = 0; j < 4; j++)
            #pragma unroll
            for (int r = 0; r < 4; r++) acc[i][j][r] = 0.f;

    for (int k0 = 0; k0 < K; k0 += 32) {
        // A tile 64x32 (row-major, K contiguous)
        {
            const int r = tid >> 3, c = (tid & 7) * 4;
            #pragma unroll
            for (int it = 0; it < 4; it++) {
                float4 v = *(const float4*)(A + (long)(m0 + r + it * 16) * lda + k0 + c);
                *(float4*)&As[(r + it * 16) * 36 + c] = v;
            }
        }
        if (NT) {  // B tile as [n][k] 64x32
            const int r = tid >> 3, c = (tid & 7) * 4;
            #pragma unroll
            for (int it = 0; it < 4; it++) {
                float4 v = *(const float4*)(B + (long)(n0 + r + it * 16) * ldb + k0 + c);
                *(float4*)&Bs[(r + it * 16) * 36 + c] = v;
            }
        } else {   // B tile as [k][n] 32x64
            const int r = tid >> 4, c = (tid & 15) * 4;
            #pragma unroll
            for (int it = 0; it < 4; it++) {
                float4 v = *(const float4*)(B + (long)(k0 + r + it * 8) * ldb + n0 + c);
                *(float4*)&Bs[(r + it * 8) * 68 + c] = v;
            }
        }
        __syncthreads();

        #pragma unroll
        for (int ks = 0; ks < 4; ks++) {
            uint32_t af[2][4];
            #pragma unroll
            for (int mf = 0; mf < 2; mf++) {
                const int rb = wm + mf * 16;
                af[mf][0] = f2tf(As[(rb + g    ) * 36 + ks * 8 + tg    ]);
                af[mf][1] = f2tf(As[(rb + g + 8) * 36 + ks * 8 + tg    ]);
                af[mf][2] = f2tf(As[(rb + g    ) * 36 + ks * 8 + tg + 4]);
                af[mf][3] = f2tf(As[(rb + g + 8) * 36 + ks * 8 + tg + 4]);
            }
            uint32_t bf[4][2];
            #pragma unroll
            for (int nf = 0; nf < 4; nf++) {
                const int cb = wn + nf * 8;
                if (NT) {
                    bf[nf][0] = f2tf(Bs[(cb + g) * 36 + ks * 8 + tg    ]);
                    bf[nf][1] = f2tf(Bs[(cb + g) * 36 + ks * 8 + tg + 4]);
                } else {
                    bf[nf][0] = f2tf(Bs[(ks * 8 + tg    ) * 68 + cb + g]);
                    bf[nf][1] = f2tf(Bs[(ks * 8 + tg + 4) * 68 + cb + g]);
                }
            }
            #pragma unroll
            for (int mf = 0; mf < 2; mf++)
                #pragma unroll
                for (int nf = 0; nf < 4; nf++)
                    mma8(acc[mf][nf], af[mf], bf[nf]);
        }
        __syncthreads();
    }

    const float NEG_INF = __int_as_float(0xff800000);
    const int mk = (EPI == 1) ? g_mask_kind : 0;
    #pragma unroll
    for (int mf = 0; mf < 2; mf++) {
        #pragma unroll
        for (int nf = 0; nf < 4; nf++) {
            const int row0 = m0 + wm + mf * 16 + g;
            const int col  = n0 + wn + nf * 8 + 2 * tg;
            #pragma unroll
            for (int half = 0; half < 2; half++) {
                const int row = row0 + half * 8;
                float v0 = acc[mf][nf][half * 2 + 0];
                float v1 = acc[mf][nf][half * 2 + 1];
                if (EPI == 1) {
                    v0 *= scale; v1 *= scale;
                    const long mi = (long)b * LL + col;
                    int m0v, m1v;
                    if (mk == 1) {
                        m0v = ((const int*)maskp)[mi];
                        m1v = ((const int*)maskp)[mi + 1];
                    } else if (mk == 2) {
                        m0v = ((const float*)maskp)[mi]     != 0.0f;
                        m1v = ((const float*)maskp)[mi + 1] != 0.0f;
                    } else {
                        m0v = ((const unsigned char*)maskp)[mi];
                        m1v = ((const unsigned char*)maskp)[mi + 1];
                    }
                    if (m0v) v0 = NEG_INF;
                    if (m1v) v1 = NEG_INF;
                }
                C[(long)row * ldc + col    ] = v0;
                C[(long)row * ldc + col + 1] = v1;
            }
        }
    }
}

// Row softmax over L=4096, in place on g_S. One block per (b,t) row.
__global__ __launch_bounds__(256) void softmax_kernel(float* __restrict__ S) {
    const long row = blockIdx.x;
    float* p = S + row * (long)LL;
    const int tid = threadIdx.x;
    __shared__ float red[8];
    const float NEG_INF = __int_as_float(0xff800000);

    float m = NEG_INF;
    for (int i = tid; i < LL; i += 256) m = fmaxf(m, p[i]);
    #pragma unroll
    for (int o = 16; o; o >>= 1) m = fmaxf(m, __shfl_xor_sync(0xffffffffu, m, o));
    if ((tid & 31) == 0) red[tid >> 5] = m;
    __syncthreads();
    float bm = NEG_INF;
    #pragma unroll
    for (int i = 0; i < 8; i++) bm = fmaxf(bm, red[i]);
    __syncthreads();

    float s = 0.f;
    for (int i = tid; i < LL; i += 256) {
        const float e = __expf(p[i] - bm);
        p[i] = e;
        s += e;
    }
    #pragma unroll
    for (int o = 16; o; o >>= 1) s += __shfl_xor_sync(0xffffffffu, s, o);
    if ((tid & 31) == 0) red[tid >> 5] = s;
    __syncthreads();
    float bs = 0.f;
    #pragma unroll
    for (int i = 0; i < 8; i++) bs += red[i];
    const float inv = 1.0f / bs;
    for (int i = tid; i < LL; i += 256) p[i] *= inv;
}

extern "C" void kernel_launch(void* const* d_in, const int* in_sizes, int n_in,
                              void* d_out, int out_size) {
    const float* H  = (const float*)d_in[0];   // [8,4096,1024]
    const float* G  = (const float*)d_in[1];   // [8,128,256]
    const void*  Mk = d_in[2];                 // [8,4096] bool (dtype detected on device)
    const float* Wk = (const float*)d_in[3];   // [1024,256]
    const float* Wq = (const float*)d_in[4];   // [256,256]
    float* Z = (float*)d_out;                  // [8,128,1024]

    void *pQ, *pQp, *pS;
    cudaGetSymbolAddress(&pQ,  g_Q);
    cudaGetSymbolAddress(&pQp, g_Qp);
    cudaGetSymbolAddress(&pS,  g_S);
    float* Q  = (float*)pQ;
    float* Qp = (float*)pQp;
    float* S  = (float*)pS;

    const float scale = 0.0625f;  // 256^-0.5

    detect_mask_kernel<<<1, 32>>>((const uint32_t*)Mk);

    // 1) Q = G @ Wq         [1024 x 256] = [1024 x 256] * [256 x 256]  (NN)
    gemm_tf32_kernel<false, 0><<<dim3(DP / 64, (BB * TT) / 64, 1), 128>>>(
        G, Wq, Q, BB * TT, DP, DG, DG, DP, DP, 0, 0, 0, nullptr, 0.f);

    // 2) Qp = Q @ Wk^T      [1024 x 1024] = [1024 x 256] * [1024 x 256]^T  (NT)
    gemm_tf32_kernel<true, 0><<<dim3(DH / 64, (BB * TT) / 64, 1), 128>>>(
        Q, Wk, Qp, BB * TT, DH, DP, DP, DP, DH, 0, 0, 0, nullptr, 0.f);

    // 3) S[b] = scale * Qp[b] @ H[b]^T, masked   per batch: [128 x 4096], K=1024  (NT)
    gemm_tf32_kernel<true, 1><<<dim3(LL / 64, TT / 64, BB), 128>>>(
        Qp, H, S, TT, LL, DH, DH, DH, LL,
        (long)TT * DH, (long)LL * DH, (long)TT * LL, Mk, scale);

    // 4) softmax rows
    softmax_kernel<<<BB * TT, 256>>>(S);

    // 5) Z[b] = S[b] @ H[b]   per batch: [128 x 1024], K=4096  (NN)
    gemm_tf32_kernel<false, 0><<<dim3(DH / 64, TT / 64, BB), 128>>>(
        S, H, Z, TT, DH, LL, LL, DH, DH,
        (long)TT * LL, (long)LL * DH, (long)TT * DH, nullptr, 0.f);
}

// round 2
// speedup vs baseline: 1.4146x; 1.4146x over previous
#include <cuda_runtime.h>
#include <cstdint>

#define BB 8
#define LL 4096
#define TT 128
#define DH 1024
#define DG 256
#define DP 256

// Scratch (static __device__ — no allocations allowed)
__device__ float g_Q[BB * TT * DP];    // 1 MB   : G @ Wq
__device__ float g_Qp[BB * TT * DH];   // 4 MB   : Q @ Wk^T  (folded query)
__device__ float g_S[BB * TT * LL];    // 16 MB  : logits -> softmax in place
__device__ int   g_mask_kind;          // 0=bool8, 1=int32, 2=float32

__device__ __forceinline__ uint32_t f2tf(float f) {
    uint32_t u;
    asm("cvt.rna.tf32.f32 %0, %1;" : "=r"(u) : "f"(f));
    return u;
}

__device__ __forceinline__ void mma8(float* c, const uint32_t* a, const uint32_t* b) {
    asm volatile(
        "mma.sync.aligned.m16n8k8.row.col.f32.tf32.tf32.f32 "
        "{%0,%1,%2,%3}, {%4,%5,%6,%7}, {%8,%9}, {%0,%1,%2,%3};"
        : "+f"(c[0]), "+f"(c[1]), "+f"(c[2]), "+f"(c[3])
        : "r"(a[0]), "r"(a[1]), "r"(a[2]), "r"(a[3]), "r"(b[0]), "r"(b[1]));
}

__device__ __forceinline__ void ldsm4(uint32_t* r, uint32_t addr) {
    asm volatile("ldmatrix.sync.aligned.m8n8.x4.shared.b16 {%0,%1,%2,%3}, [%4];"
                 : "=r"(r[0]), "=r"(r[1]), "=r"(r[2]), "=r"(r[3]) : "r"(addr));
}

// Detect how the bool mask was materialized by the harness.
__global__ void detect_mask_kernel(const uint32_t* __restrict__ m) {
    if (threadIdx.x == 0 && blockIdx.x == 0) {
        bool isInt = true, isFloat = true;
        for (int i = 0; i < 256; i++) {
            uint32_t v = m[i];
            if (v != 0u && v != 1u) isInt = false;
            if (v != 0u && v != 0x3f800000u) isFloat = false;
        }
        g_mask_kind = isInt ? 1 : (isFloat ? 2 : 0);
    }
}

// tf32 tile GEMM v2:  C = A(MxK) * op(B).  NT: B is [N,K] (C=A*B^T), NN: B is [K,N].
// BM=128, BN=64, BK=32, 128 threads (4 warps 2x2, warp tile 64x32).
// SMEM holds pre-converted tf32. A frags + NT B frags via ldmatrix.
// EPI: 0 = plain store, 1 = scale + mask(-inf) store (logits).
template <bool NT, int EPI>
__global__ __launch_bounds__(128) void gemm2_kernel(
    const float* __restrict__ A, const float* __restrict__ B, float* __restrict__ C,
    int N, int K, int lda, int ldb, int ldc,
    long strideA, long strideB, long strideC,
    const void* __restrict__ maskp, float scale)
{
    const int b = blockIdx.z;
    A += (long)b * strideA;
    B += (long)b * strideB;
    C += (long)b * strideC;

    __shared__ uint32_t As[128 * 36];                 // [m][k], ld=36
    __shared__ uint32_t Bs[NT ? 64 * 36 : 32 * 68];   // NT: [n][k] ld=36, NN: [k][n] ld=68

    const int tid  = threadIdx.x;
    const int m0   = blockIdx.y * 128;
    const int n0   = blockIdx.x * 64;
    const int warp = tid >> 5, lane = tid & 31;
    const int wm = (warp >> 1) * 64, wn = (warp & 1) * 32;
    const int g  = lane >> 2, tg = lane & 3;

    // staging indices
    const int ar = tid >> 3, ac = (tid & 7) * 4;               // A: 128x32
    const int br = NT ? (tid >> 3) : (tid >> 4);
    const int bc = NT ? (tid & 7) * 4 : (tid & 15) * 4;

    float acc[4][4][4];
    #pragma unroll
    for (int i = 0; i < 4; i++)
        #pragma unroll
        for (int j = 0; j < 4; j++)
            #pragma unroll
            for (int r = 0; r < 4; r++) acc[i][j][r] = 0.f;

    // fragment ldmatrix base addresses (byte, shared space)
    const uint32_t asB = (uint32_t)__cvta_generic_to_shared(As);
    const uint32_t bsB = (uint32_t)__cvta_generic_to_shared(Bs);
    const uint32_t aBase = asB + (((wm + (lane & 15)) * 36 + ((lane >> 4) << 2)) << 2);
    const uint32_t bBase = bsB + (((wn + (lane & 7) + ((lane & 16) >> 1)) * 36 + ((lane & 8) >> 1)) << 2);

    float4 aF[8], bF[4];

    auto ldgA = [&](int k0) {
        #pragma unroll
        for (int it = 0; it < 8; it++)
            aF[it] = *(const float4*)(A + (long)(m0 + ar + 16 * it) * lda + k0 + ac);
    };
    auto ldgB = [&](int k0) {
        #pragma unroll
        for (int it = 0; it < 4; it++) {
            if (NT) bF[it] = *(const float4*)(B + (long)(n0 + br + 16 * it) * ldb + k0 + bc);
            else    bF[it] = *(const float4*)(B + (long)(k0 + br + 8 * it) * ldb + n0 + bc);
        }
    };
    auto stsAB = [&]() {
        #pragma unroll
        for (int it = 0; it < 8; it++) {
            uint4 u = make_uint4(f2tf(aF[it].x), f2tf(aF[it].y), f2tf(aF[it].z), f2tf(aF[it].w));
            *(uint4*)&As[(ar + 16 * it) * 36 + ac] = u;
        }
        #pragma unroll
        for (int it = 0; it < 4; it++) {
            uint4 u = make_uint4(f2tf(bF[it].x), f2tf(bF[it].y), f2tf(bF[it].z), f2tf(bF[it].w));
            if (NT) *(uint4*)&Bs[(br + 16 * it) * 36 + bc] = u;
            else    *(uint4*)&Bs[(br + 8 * it) * 68 + bc] = u;
        }
    };
    auto compute = [&]() {
        #pragma unroll
        for (int ks = 0; ks < 4; ks++) {
            uint32_t af[4][4];
            #pragma unroll
            for (int mf = 0; mf < 4; mf++)
                ldsm4(af[mf], aBase + mf * (16 * 36 * 4) + ks * 32);
            uint32_t bf[4][2];
            if (NT) {
                #pragma unroll
                for (int p = 0; p < 2; p++) {
                    uint32_t r[4];
                    ldsm4(r, bBase + p * (16 * 36 * 4) + ks * 32);
                    bf[2 * p][0] = r[0]; bf[2 * p][1] = r[1];
                    bf[2 * p + 1][0] = r[2]; bf[2 * p + 1][1] = r[3];
                }
            } else {
                #pragma unroll
                for (int nf = 0; nf < 4; nf++) {
                    bf[nf][0] = Bs[(ks * 8 + tg) * 68 + wn + nf * 8 + g];
                    bf[nf][1] = Bs[(ks * 8 + tg + 4) * 68 + wn + nf * 8 + g];
                }
            }
            #pragma unroll
            for (int mf = 0; mf < 4; mf++)
                #pragma unroll
                for (int nf = 0; nf < 4; nf++)
                    mma8(acc[mf][nf], af[mf], bf[nf]);
        }
    };

    const int kIter = K / 32;
    ldgA(0); ldgB(0);
    stsAB();
    __syncthreads();
    for (int i = 0; i < kIter; i++) {
        if (i + 1 < kIter) { ldgA((i + 1) * 32); ldgB((i + 1) * 32); }
        compute();
        __syncthreads();
        if (i + 1 < kIter) {
            stsAB();
            __syncthreads();
        }
    }

    const float NEG_INF = __int_as_float(0xff800000);
    const int mk = (EPI == 1) ? g_mask_kind : 0;
    #pragma unroll
    for (int mf = 0; mf < 4; mf++) {
        #pragma unroll
        for (int nf = 0; nf < 4; nf++) {
            const int row0 = m0 + wm + mf * 16 + g;
            const int col  = n0 + wn + nf * 8 + 2 * tg;
            #pragma unroll
            for (int half = 0; half < 2; half++) {
                const int row = row0 + half * 8;
                float v0 = acc[mf][nf][half * 2 + 0];
                float v1 = acc[mf][nf][half * 2 + 1];
                if (EPI == 1) {
                    v0 *= scale; v1 *= scale;
                    const long mi = (long)b * LL + col;
                    int m0v, m1v;
                    if (mk == 1) {
                        m0v = ((const int*)maskp)[mi];
                        m1v = ((const int*)maskp)[mi + 1];
                    } else if (mk == 2) {
                        m0v = ((const float*)maskp)[mi]     != 0.0f;
                        m1v = ((const float*)maskp)[mi + 1] != 0.0f;
                    } else {
                        m0v = ((const unsigned char*)maskp)[mi];
                        m1v = ((const unsigned char*)maskp)[mi + 1];
                    }
                    if (m0v) v0 = NEG_INF;
                    if (m1v) v1 = NEG_INF;
                }
                *(float2*)&C[(long)row * ldc + col] = make_float2(v0, v1);
            }
        }
    }
}

// Single-pass register-resident softmax over L=4096. One block of 256 per row.
__global__ __launch_bounds__(256) void softmax_kernel(float* __restrict__ S) {
    float4* p = (float4*)(S + (long)blockIdx.x * LL);
    const int tid = threadIdx.x;
    __shared__ float red[8];
    const float NEG_INF = __int_as_float(0xff800000);

    float4 v[4];
    #pragma unroll
    for (int j = 0; j < 4; j++) v[j] = p[tid + 256 * j];

    float m = NEG_INF;
    #pragma unroll
    for (int j = 0; j < 4; j++)
        m = fmaxf(m, fmaxf(fmaxf(v[j].x, v[j].y), fmaxf(v[j].z, v[j].w)));
    #pragma unroll
    for (int o = 16; o; o >>= 1) m = fmaxf(m, __shfl_xor_sync(0xffffffffu, m, o));
    if ((tid & 31) == 0) red[tid >> 5] = m;
    __syncthreads();
    float bm = NEG_INF;
    #pragma unroll
    for (int i = 0; i < 8; i++) bm = fmaxf(bm, red[i]);
    __syncthreads();

    float s = 0.f;
    #pragma unroll
    for (int j = 0; j < 4; j++) {
        v[j].x = __expf(v[j].x - bm); v[j].y = __expf(v[j].y - bm);
        v[j].z = __expf(v[j].z - bm); v[j].w = __expf(v[j].w - bm);
        s += v[j].x + v[j].y + v[j].z + v[j].w;
    }
    #pragma unroll
    for (int o = 16; o; o >>= 1) s += __shfl_xor_sync(0xffffffffu, s, o);
    if ((tid & 31) == 0) red[tid >> 5] = s;
    __syncthreads();
    float bs = 0.f;
    #pragma unroll
    for (int i = 0; i < 8; i++) bs += red[i];
    const float inv = 1.0f / bs;
    #pragma unroll
    for (int j = 0; j < 4; j++) {
        v[j].x *= inv; v[j].y *= inv; v[j].z *= inv; v[j].w *= inv;
        p[tid + 256 * j] = v[j];
    }
}

extern "C" void kernel_launch(void* const* d_in, const int* in_sizes, int n_in,
                              void* d_out, int out_size) {
    const float* H  = (const float*)d_in[0];   // [8,4096,1024]
    const float* G  = (const float*)d_in[1];   // [8,128,256]
    const void*  Mk = d_in[2];                 // [8,4096] bool (dtype detected on device)
    const float* Wk = (const float*)d_in[3];   // [1024,256]
    const float* Wq = (const float*)d_in[4];   // [256,256]
    float* Z = (float*)d_out;                  // [8,128,1024]

    void *pQ, *pQp, *pS;
    cudaGetSymbolAddress(&pQ,  g_Q);
    cudaGetSymbolAddress(&pQp, g_Qp);
    cudaGetSymbolAddress(&pS,  g_S);
    float* Q  = (float*)pQ;
    float* Qp = (float*)pQp;
    float* S  = (float*)pS;

    const float scale = 0.0625f;  // 256^-0.5

    detect_mask_kernel<<<1, 32>>>((const uint32_t*)Mk);

    // 1) Q = G @ Wq         [1024 x 256] = [1024 x 256] * [256 x 256]  (NN)
    gemm2_kernel<false, 0><<<dim3(DP / 64, (BB * TT) / 128, 1), 128>>>(
        G, Wq, Q, DP, DG, DG, DP, DP, 0, 0, 0, nullptr, 0.f);

    // 2) Qp = Q @ Wk^T      [1024 x 1024] = [1024 x 256] * [1024 x 256]^T  (NT)
    gemm2_kernel<true, 0><<<dim3(DH / 64, (BB * TT) / 128, 1), 128>>>(
        Q, Wk, Qp, DH, DP, DP, DP, DH, 0, 0, 0, nullptr, 0.f);

    // 3) S[b] = scale * Qp[b] @ H[b]^T, masked   per batch: [128 x 4096], K=1024  (NT)
    gemm2_kernel<true, 1><<<dim3(LL / 64, 1, BB), 128>>>(
        Qp, H, S, LL, DH, DH, DH, LL,
        (long)TT * DH, (long)LL * DH, (long)TT * LL, Mk, scale);

    // 4) softmax rows
    softmax_kernel<<<BB * TT, 256>>>(S);

    // 5) Z[b] = S[b] @ H[b]   per batch: [128 x 1024], K=4096  (NN)
    gemm2_kernel<false, 0><<<dim3(DH / 64, 1, BB), 128>>>(
        S, H, Z, DH, LL, LL, DH, DH,
        (long)TT * LL, (long)LL * DH, (long)TT * DH, nullptr, 0.f);
}

// round 3
// speedup vs baseline: 1.7559x; 1.2413x over previous
#include <cuda_runtime.h>
#include <cstdint>

#define BB 8
#define LL 4096
#define TT 128
#define DH 1024
#define DG 256
#define DP 256

// Scratch (static __device__ — no allocations allowed)
__device__ float g_Q[BB * TT * DP];        // 1 MB
__device__ float g_Qp[BB * TT * DH];       // 4 MB
__device__ float g_S[BB * TT * LL];        // 16 MB
__device__ float g_P[4][BB * TT * DH];     // 16 MB split-K partials for Z
__device__ int   g_mask_kind;

__device__ __forceinline__ uint32_t f2tf(float f) {
    uint32_t u;
    asm("cvt.rna.tf32.f32 %0, %1;" : "=r"(u) : "f"(f));
    return u;
}
__device__ __forceinline__ uint4 cvt4(float4 v) {
    return make_uint4(f2tf(v.x), f2tf(v.y), f2tf(v.z), f2tf(v.w));
}

__device__ __forceinline__ void mma8(float* c, const uint32_t* a, const uint32_t* b) {
    asm volatile(
        "mma.sync.aligned.m16n8k8.row.col.f32.tf32.tf32.f32 "
        "{%0,%1,%2,%3}, {%4,%5,%6,%7}, {%8,%9}, {%0,%1,%2,%3};"
        : "+f"(c[0]), "+f"(c[1]), "+f"(c[2]), "+f"(c[3])
        : "r"(a[0]), "r"(a[1]), "r"(a[2]), "r"(a[3]), "r"(b[0]), "r"(b[1]));
}
__device__ __forceinline__ void ldsm4(uint32_t* r, uint32_t addr) {
    asm volatile("ldmatrix.sync.aligned.m8n8.x4.shared.b16 {%0,%1,%2,%3}, [%4];"
                 : "=r"(r[0]), "=r"(r[1]), "=r"(r[2]), "=r"(r[3]) : "r"(addr));
}

__global__ void detect_mask_kernel(const uint32_t* __restrict__ m) {
    if (threadIdx.x == 0 && blockIdx.x == 0) {
        bool isInt = true, isFloat = true;
        for (int i = 0; i < 256; i++) {
            uint32_t v = m[i];
            if (v != 0u && v != 1u) isInt = false;
            if (v != 0u && v != 0x3f800000u) isFloat = false;
        }
        g_mask_kind = isInt ? 1 : (isFloat ? 2 : 0);
    }
}

// tf32 GEMM v3. C = A(MxK) * op(B). NT: B is [N,K]; NN: B is [K,N].
// BM=128, BN=128, BK=16, 256 threads (8 warps 2x4, warp tile 64x32).
// Double-buffered SMEM (tf32 pre-converted), one __syncthreads per K-iter.
// EPI: 0 plain store, 1 scale+mask(-inf).  SPLITK: blockIdx.y = K-quarter.
template <bool NT, int EPI, bool SPLITK>
__global__ __launch_bounds__(256, 2) void gemm3_kernel(
    const float* __restrict__ A, const float* __restrict__ B, float* __restrict__ C,
    int K, int lda, int ldb, int ldc,
    long strideA, long strideB, long strideC, long splitStride,
    const void* __restrict__ maskp, float scale)
{
    const int b = blockIdx.z;
    A += (long)b * strideA;
    B += (long)b * strideB;
    C += (long)b * strideC;
    if (SPLITK) C += (long)blockIdx.y * splitStride;

    __shared__ uint32_t As[2][128 * 20];
    __shared__ uint32_t Bs[2][NT ? 128 * 20 : 16 * 132];

    const int tid  = threadIdx.x;
    const int m0   = SPLITK ? 0 : blockIdx.y * 128;
    const int n0   = blockIdx.x * 128;
    const int warp = tid >> 5, lane = tid & 31;
    const int wm = (warp >> 2) * 64, wn = (warp & 3) * 32;
    const int g  = lane >> 2, tg = lane & 3;

    // staging indices
    const int ar = tid >> 2, acw = (tid & 3) * 4;                  // A: 128x16, 2 float4/thread
    const int br = tid >> 2, bcw = (tid & 3) * 4;                  // B NT: same
    const int bk = tid >> 4, bnw = (tid & 15) * 4;                 // B NN: 16x128

    float acc[4][4][4];
    #pragma unroll
    for (int i = 0; i < 4; i++)
        #pragma unroll
        for (int j = 0; j < 4; j++)
            #pragma unroll
            for (int r = 0; r < 4; r++) acc[i][j][r] = 0.f;

    const uint32_t asB = (uint32_t)__cvta_generic_to_shared(&As[0][0]);
    const uint32_t bsB = (uint32_t)__cvta_generic_to_shared(&Bs[0][0]);
    const uint32_t aBase0 = asB + (((wm + (lane & 15)) * 20 + ((lane >> 4) << 2)) << 2);
    const uint32_t bBase0 = bsB + (((wn + (lane & 7) + ((lane & 16) >> 1)) * 20 + ((lane & 8) >> 1)) << 2);
    const uint32_t A_STG = 128 * 20 * 4;
    const uint32_t B_STG = (NT ? 128 * 20 : 16 * 132) * 4;

    float4 aF[2], bF[2];

    auto ldg = [&](int k0) {
        #pragma unroll
        for (int i = 0; i < 2; i++)
            aF[i] = *(const float4*)(A + (long)(m0 + ar + 64 * i) * lda + k0 + acw);
        #pragma unroll
        for (int i = 0; i < 2; i++) {
            if (NT) bF[i] = *(const float4*)(B + (long)(n0 + br + 64 * i) * ldb + k0 + bcw);
            else    bF[i] = *(const float4*)(B + (long)(k0 + bk) * ldb + n0 + bnw + 64 * i);
        }
    };
    auto sts = [&](int buf) {
        #pragma unroll
        for (int i = 0; i < 2; i++)
            *(uint4*)&As[buf][(ar + 64 * i) * 20 + acw] = cvt4(aF[i]);
        #pragma unroll
        for (int i = 0; i < 2; i++) {
            if (NT) *(uint4*)&Bs[buf][(br + 64 * i) * 20 + bcw] = cvt4(bF[i]);
            else    *(uint4*)&Bs[buf][bk * 132 + bnw + 64 * i] = cvt4(bF[i]);
        }
    };
    auto compute = [&](int buf) {
        const uint32_t aB = aBase0 + buf * A_STG;
        const uint32_t bB = bBase0 + buf * B_STG;
        #pragma unroll
        for (int ks = 0; ks < 2; ks++) {
            uint32_t af[4][4];
            #pragma unroll
            for (int mf = 0; mf < 4; mf++)
                ldsm4(af[mf], aB + mf * (16 * 20 * 4) + ks * 32);
            uint32_t bf[4][2];
            if (NT) {
                #pragma unroll
                for (int p = 0; p < 2; p++) {
                    uint32_t r[4];
                    ldsm4(r, bB + p * (16 * 20 * 4) + ks * 32);
                    bf[2 * p][0] = r[0]; bf[2 * p][1] = r[1];
                    bf[2 * p + 1][0] = r[2]; bf[2 * p + 1][1] = r[3];
                }
            } else {
                #pragma unroll
                for (int nf = 0; nf < 4; nf++) {
                    bf[nf][0] = Bs[buf][(ks * 8 + tg) * 132 + wn + nf * 8 + g];
                    bf[nf][1] = Bs[buf][(ks * 8 + tg + 4) * 132 + wn + nf * 8 + g];
                }
            }
            #pragma unroll
            for (int mf = 0; mf < 4; mf++)
                #pragma unroll
                for (int nf = 0; nf < 4; nf++)
                    mma8(acc[mf][nf], af[mf], bf[nf]);
        }
    };

    const int kBeg  = SPLITK ? blockIdx.y * (K >> 2) : 0;
    const int nIter = (SPLITK ? (K >> 2) : K) >> 4;

    ldg(kBeg);
    sts(0);
    __syncthreads();
    for (int i = 0; i < nIter; i++) {
        if (i + 1 < nIter) ldg(kBeg + (i + 1) * 16);
        compute(i & 1);
        if (i + 1 < nIter) {
            sts((i + 1) & 1);
        }
        __syncthreads();
    }

    const float NEG_INF = __int_as_float(0xff800000);
    const int mk = (EPI == 1) ? g_mask_kind : 0;
    #pragma unroll
    for (int mf = 0; mf < 4; mf++) {
        #pragma unroll
        for (int nf = 0; nf < 4; nf++) {
            const int row0 = m0 + wm + mf * 16 + g;
            const int col  = n0 + wn + nf * 8 + 2 * tg;
            #pragma unroll
            for (int half = 0; half < 2; half++) {
                const int row = row0 + half * 8;
                float v0 = acc[mf][nf][half * 2 + 0];
                float v1 = acc[mf][nf][half * 2 + 1];
                if (EPI == 1) {
                    v0 *= scale; v1 *= scale;
                    const long mi = (long)b * LL + col;
                    int m0v, m1v;
                    if (mk == 1) {
                        m0v = ((const int*)maskp)[mi];
                        m1v = ((const int*)maskp)[mi + 1];
                    } else if (mk == 2) {
                        m0v = ((const float*)maskp)[mi]     != 0.0f;
                        m1v = ((const float*)maskp)[mi + 1] != 0.0f;
                    } else {
                        m0v = ((const unsigned char*)maskp)[mi];
                        m1v = ((const unsigned char*)maskp)[mi + 1];
                    }
                    if (m0v) v0 = NEG_INF;
                    if (m1v) v1 = NEG_INF;
                }
                *(float2*)&C[(long)row * ldc + col] = make_float2(v0, v1);
            }
        }
    }
}

// Sum the 4 split-K partials into Z.
__global__ __launch_bounds__(256) void reduce4_kernel(const float4* __restrict__ P, float4* __restrict__ Z) {
    const int idx = blockIdx.x * 256 + threadIdx.x;
    const int n4 = BB * TT * DH / 4;
    float4 a = P[idx], b = P[idx + n4], c = P[idx + 2 * n4], d = P[idx + 3 * n4];
    float4 o;
    o.x = (a.x + b.x) + (c.x + d.x);
    o.y = (a.y + b.y) + (c.y + d.y);
    o.z = (a.z + b.z) + (c.z + d.z);
    o.w = (a.w + b.w) + (c.w + d.w);
    Z[idx] = o;
}

// Single-pass register-resident softmax over L=4096. One block of 256 per row.
__global__ __launch_bounds__(256) void softmax_kernel(float* __restrict__ S) {
    float4* p = (float4*)(S + (long)blockIdx.x * LL);
    const int tid = threadIdx.x;
    __shared__ float red[8];
    const float NEG_INF = __int_as_float(0xff800000);

    float4 v[4];
    #pragma unroll
    for (int j = 0; j < 4; j++) v[j] = p[tid + 256 * j];

    float m = NEG_INF;
    #pragma unroll
    for (int j = 0; j < 4; j++)
        m = fmaxf(m, fmaxf(fmaxf(v[j].x, v[j].y), fmaxf(v[j].z, v[j].w)));
    #pragma unroll
    for (int o = 16; o; o >>= 1) m = fmaxf(m, __shfl_xor_sync(0xffffffffu, m, o));
    if ((tid & 31) == 0) red[tid >> 5] = m;
    __syncthreads();
    float bm = NEG_INF;
    #pragma unroll
    for (int i = 0; i < 8; i++) bm = fmaxf(bm, red[i]);
    __syncthreads();

    float s = 0.f;
    #pragma unroll
    for (int j = 0; j < 4; j++) {
        v[j].x = __expf(v[j].x - bm); v[j].y = __expf(v[j].y - bm);
        v[j].z = __expf(v[j].z - bm); v[j].w = __expf(v[j].w - bm);
        s += v[j].x + v[j].y + v[j].z + v[j].w;
    }
    #pragma unroll
    for (int o = 16; o; o >>= 1) s += __shfl_xor_sync(0xffffffffu, s, o);
    if ((tid & 31) == 0) red[tid >> 5] = s;
    __syncthreads();
    float bs = 0.f;
    #pragma unroll
    for (int i = 0; i < 8; i++) bs += red[i];
    const float inv = 1.0f / bs;
    #pragma unroll
    for (int j = 0; j < 4; j++) {
        v[j].x *= inv; v[j].y *= inv; v[j].z *= inv; v[j].w *= inv;
        p[tid + 256 * j] = v[j];
    }
}

extern "C" void kernel_launch(void* const* d_in, const int* in_sizes, int n_in,
                              void* d_out, int out_size) {
    const float* H  = (const float*)d_in[0];   // [8,4096,1024]
    const float* G  = (const float*)d_in[1];   // [8,128,256]
    const void*  Mk = d_in[2];                 // [8,4096] bool (dtype detected on device)
    const float* Wk = (const float*)d_in[3];   // [1024,256]
    const float* Wq = (const float*)d_in[4];   // [256,256]
    float* Z = (float*)d_out;                  // [8,128,1024]

    void *pQ, *pQp, *pS, *pP;
    cudaGetSymbolAddress(&pQ,  g_Q);
    cudaGetSymbolAddress(&pQp, g_Qp);
    cudaGetSymbolAddress(&pS,  g_S);
    cudaGetSymbolAddress(&pP,  g_P);
    float* Q  = (float*)pQ;
    float* Qp = (float*)pQp;
    float* S  = (float*)pS;
    float* P  = (float*)pP;

    const float scale = 0.0625f;  // 256^-0.5
    const long ZELEM = (long)BB * TT * DH;

    detect_mask_kernel<<<1, 32>>>((const uint32_t*)Mk);

    // 1) Q = G @ Wq   [1024 x 256] (NN), K=256
    gemm3_kernel<false, 0, false><<<dim3(DP / 128, (BB * TT) / 128, 1), 256>>>(
        G, Wq, Q, DG, DG, DP, DP, 0, 0, 0, 0, nullptr, 0.f);

    // 2) Qp = Q @ Wk^T  [1024 x 1024] (NT), K=256
    gemm3_kernel<true, 0, false><<<dim3(DH / 128, (BB * TT) / 128, 1), 256>>>(
        Q, Wk, Qp, DP, DP, DP, DH, 0, 0, 0, 0, nullptr, 0.f);

    // 3) S[b] = scale * Qp[b] @ H[b]^T, masked  [128 x 4096] per batch (NT), K=1024
    gemm3_kernel<true, 1, false><<<dim3(LL / 128, 1, BB), 256>>>(
        Qp, H, S, DH, DH, DH, LL,
        (long)TT * DH, (long)LL * DH, (long)TT * LL, 0, Mk, scale);

    // 4) softmax rows
    softmax_kernel<<<BB * TT, 256>>>(S);

    // 5) P[q] = S[b] @ H[b] over K-quarter q  [128 x 1024] per batch (NN), split-K 4
    gemm3_kernel<false, 0, true><<<dim3(DH / 128, 4, BB), 256>>>(
        S, H, P, LL, LL, DH, DH,
        (long)TT * LL, (long)LL * DH, (long)TT * DH, ZELEM, nullptr, 0.f);

    // 6) Z = sum of partials
    reduce4_kernel<<<(int)(ZELEM / 4 / 256), 256>>>((const float4*)P, (float4*)Z);
}